// round 15
// baseline (speedup 1.0000x reference)
#include <cuda_runtime.h>
#include <cuda_fp16.h>
#include <math.h>

#define NN 50000
#define EE 600000
#define DDIM 128
#define HH 8
#define NB 196   // ceil(NN/256) scan blocks
#define NBLK 196 // N_BLOCKS == NB

// ---------------- scratch (static device memory; no allocs) ----------------
static __device__ float  g_h[NN * DDIM];           // LN1 output (float, residual)
static __device__ __half g_hh[NN * DDIM];          // LN1 output (half, GEMM A)
static __device__ __half g_qkv[NN * 3 * DDIM];     // [N][3][H][16] half
static __device__ __half g_agg[NN * DDIM];         // aggregated msgs (half)
static __device__ float  g_x[NN * DDIM];           // residual stream
static __device__ __half g_yh[NN * DDIM];          // LN2 output (half)
static __device__ int    g_deg[NN];
static __device__ int    g_off[NN + 1];
static __device__ int    g_pos[NN];
static __device__ int    g_esrc[EE];               // src node per CSR slot
static __device__ float  g_edp[EE * HH];           // dist+path per CSR slot
static __device__ int    g_bsum[NB];

// ---------------- half pack/unpack helpers ----------------
static __device__ __forceinline__ unsigned fh2(float lo, float hi) {
    __half2 hv = __floats2half2_rn(lo, hi);
    return *reinterpret_cast<unsigned*>(&hv);
}
static __device__ __forceinline__ void ldh8(const __half* p, float* o) {
    uint4 u = *(const uint4*)p;
    __half2* hp = (__half2*)&u;
    #pragma unroll
    for (int j = 0; j < 4; j++) {
        float2 f = __half22float2(hp[j]);
        o[2 * j] = f.x; o[2 * j + 1] = f.y;
    }
}

// ---------------- CSR build ----------------
__global__ void hist_kernel(const int* __restrict__ dst) {
    int e = blockIdx.x * blockDim.x + threadIdx.x;
    if (e < EE) atomicAdd(&g_deg[dst[e]], 1);
}
__global__ void scanA_kernel() {
    __shared__ int sh[256];
    int t = threadIdx.x;
    int i = blockIdx.x * 256 + t;
    int val = (i < NN) ? g_deg[i] : 0;
    sh[t] = val;
    #pragma unroll
    for (int o = 1; o < 256; o <<= 1) {
        __syncthreads();
        int x = (t >= o) ? sh[t - o] : 0;
        __syncthreads();
        sh[t] += x;
    }
    __syncthreads();
    int excl = sh[t] - val;
    if (i < NN) g_off[i] = excl;
    if (t == 255) g_bsum[blockIdx.x] = sh[255];
}
__global__ void scanBC_kernel() {
    __shared__ int sh[256];
    int t = threadIdx.x;
    sh[t] = (t < blockIdx.x && t < NB) ? g_bsum[t] : 0;
    __syncthreads();
    #pragma unroll
    for (int o = 128; o > 0; o >>= 1) {
        if (t < o) sh[t] += sh[t + o];
        __syncthreads();
    }
    int base = sh[0];
    int i = blockIdx.x * 256 + t;
    if (i < NN) {
        int v = g_off[i] + base;
        g_off[i] = v;
        g_pos[i] = v;
    }
    if (i == 0) g_off[NN] = EE;
}
__global__ void scatter_kernel(const int* __restrict__ src,
                               const int* __restrict__ dst,
                               const float* __restrict__ dist,
                               const float* __restrict__ path) {
    int e = blockIdx.x * blockDim.x + threadIdx.x;
    if (e >= EE) return;
    int d = dst[e];
    int p = atomicAdd(&g_pos[d], 1);
    g_esrc[p] = src[e];
    float4 d0 = *(const float4*)(dist + (size_t)e * 8);
    float4 d1 = *(const float4*)(dist + (size_t)e * 8 + 4);
    float4 p0 = *(const float4*)(path + (size_t)e * 8);
    float4 p1 = *(const float4*)(path + (size_t)e * 8 + 4);
    *(float4*)(g_edp + (size_t)p * 8) =
        make_float4(d0.x + p0.x, d0.y + p0.y, d0.z + p0.z, d0.w + p0.w);
    *(float4*)(g_edp + (size_t)p * 8 + 4) =
        make_float4(d1.x + p1.x, d1.y + p1.y, d1.z + p1.z, d1.w + p1.w);
}

// ---------------- merged zero_deg + LN1 ----------------
__global__ void zero_ln_kernel(const float* __restrict__ in,
                               const float* __restrict__ g,
                               const float* __restrict__ b,
                               float* __restrict__ outf,
                               __half* __restrict__ outh) {
    if (blockIdx.x < NBLK) {
        int i = blockIdx.x * 256 + threadIdx.x;
        if (i < NN) g_deg[i] = 0;
        return;
    }
    int wid  = ((blockIdx.x - NBLK) * 256 + threadIdx.x) >> 5;
    int lane = threadIdx.x & 31;
    if (wid >= NN) return;
    const float4* row = (const float4*)(in + (size_t)wid * DDIM);
    float4 x = row[lane];
    float s  = x.x + x.y + x.z + x.w;
    float s2 = x.x * x.x + x.y * x.y + x.z * x.z + x.w * x.w;
    #pragma unroll
    for (int o = 16; o > 0; o >>= 1) {
        s  += __shfl_xor_sync(0xFFFFFFFFu, s,  o);
        s2 += __shfl_xor_sync(0xFFFFFFFFu, s2, o);
    }
    float mu  = s  * (1.0f / 128.0f);
    float var = s2 * (1.0f / 128.0f) - mu * mu;
    float r   = rsqrtf(var + 1e-5f);
    float4 gg = ((const float4*)g)[lane];
    float4 bb = ((const float4*)b)[lane];
    float4 o4;
    o4.x = (x.x - mu) * r * gg.x + bb.x;
    o4.y = (x.y - mu) * r * gg.y + bb.y;
    o4.z = (x.z - mu) * r * gg.z + bb.z;
    o4.w = (x.w - mu) * r * gg.w + bb.w;
    ((float4*)(outf + (size_t)wid * DDIM))[lane] = o4;
    *(uint2*)(outh + (size_t)wid * DDIM + lane * 4) =
        make_uint2(fh2(o4.x, o4.y), fh2(o4.z, o4.w));
}

// ---------------- fused attention: warp = dst, 2 edges x 3-deep pipeline ----
#define ALOAD2(s, i) do {                                                   \
    int off_ = gho + ((i) << 1);                                            \
    int idx_ = beg + (off_ < cnt ? off_ : cnt - 1);                         \
    int s_ = g_esrc[idx_];                                                  \
    ldh8(g_qkv + (size_t)s_ * 384 + l16 * 8, q##s);                         \
    ldh8(g_qkv + (size_t)s_ * 384 + 256 + l16 * 8, v##s);                   \
    dp##s = (off_ < cnt) ? g_edp[(size_t)idx_ * 8 + h2] : -1e38f;           \
} while (0)

#define ASTEP2(s) do {                                                      \
    float p_ = q##s[0] * kv[0] + q##s[1] * kv[1] + q##s[2] * kv[2]          \
             + q##s[3] * kv[3] + q##s[4] * kv[4] + q##s[5] * kv[5]          \
             + q##s[6] * kv[6] + q##s[7] * kv[7];                           \
    float dot_ = p_ + __shfl_xor_sync(0xFFFFFFFFu, p_, 1);                  \
    float a_ = dot_ + dp##s;                                                \
    float mn_ = fmaxf(m, a_);                                               \
    float corr_ = __expf(m - mn_);                                          \
    float pw_ = __expf(a_ - mn_);                                           \
    den = den * corr_ + pw_;                                                \
    _Pragma("unroll")                                                       \
    for (int j_ = 0; j_ < 8; j_++)                                          \
        acc[j_] = acc[j_] * corr_ + v##s[j_] * pw_;                         \
    m = mn_;                                                                \
} while (0)

__global__ void attn_kernel() {
    int w = (blockIdx.x * blockDim.x + threadIdx.x) >> 5;
    if (w >= NN) return;
    int lane = threadIdx.x & 31;
    int gho = lane >> 4;     // half-warp id (edge parity)
    int l16 = lane & 15;     // lane within half: dims [l16*8, l16*8+8)
    int h2  = l16 >> 1;      // head
    int beg = g_off[w], end = g_off[w + 1];
    int cnt = end - beg;     // warp-uniform
    float kv[8];
    ldh8(g_qkv + (size_t)w * 384 + 128 + l16 * 8, kv);
    float acc[8];
    #pragma unroll
    for (int j = 0; j < 8; j++) acc[j] = 0.f;
    float m = -1e30f, den = 0.f;

    int steps = (cnt + 1) >> 1;   // warp-uniform iteration count
    if (steps > 0) {
        float q0[8], v0[8], q1[8], v1[8], q2[8], v2[8];
        float dp0 = 0.f, dp1 = 0.f, dp2 = 0.f;
        ALOAD2(0, 0);
        if (steps > 1) ALOAD2(1, 1);
        if (steps > 2) ALOAD2(2, 2);
        int i = 0;
        while (i + 3 <= steps) {
            ASTEP2(0);
            if (i + 3 < steps) ALOAD2(0, i + 3);
            ASTEP2(1);
            if (i + 4 < steps) ALOAD2(1, i + 4);
            ASTEP2(2);
            if (i + 5 < steps) ALOAD2(2, i + 5);
            i += 3;
        }
        int rem = steps - i;   // 0..2
        if (rem > 0) ASTEP2(0);
        if (rem > 1) ASTEP2(1);
    }

    // merge the two half-warp softmax states (exact)
    float mo  = __shfl_xor_sync(0xFFFFFFFFu, m, 16);
    float dno = __shfl_xor_sync(0xFFFFFFFFu, den, 16);
    float mn  = fmaxf(m, mo);
    float cs  = __expf(m - mn);
    float co  = __expf(mo - mn);
    float dtot = den * cs + dno * co;
    #pragma unroll
    for (int j = 0; j < 8; j++) {
        float ao = __shfl_xor_sync(0xFFFFFFFFu, acc[j], 16);
        acc[j] = acc[j] * cs + ao * co;
    }
    float inv = (dtot > 0.f) ? (1.0f / dtot) : 0.f;
    if (gho == 0) {
        uint4 o;
        o.x = fh2(acc[0] * inv, acc[1] * inv);
        o.y = fh2(acc[2] * inv, acc[3] * inv);
        o.z = fh2(acc[4] * inv, acc[5] * inv);
        o.w = fh2(acc[6] * inv, acc[7] * inv);
        *(uint4*)(g_agg + (size_t)w * DDIM + l16 * 8) = o;
    }
}

// ---------------- FP16 tensor-core GEMM (m16n8k16, fp32 accum) ----------------
// EPI==0 (qkv): writes half C, q-scale on col-block 0.
// EPI==1 (in_proj): writes float C = acc+bias+res AND does fused LayerNorm
//   over the full 128-col rows (M must be 128), writing half Yh. Reuses the
//   smem tiles as float xs[128][132] in the epilogue.
#define SA 20
#define SB 136
#define ABUF (128 * SA)   // 2560 u32
#define BBUF (16 * SB)    // 2176 u32
#define GM_SMEM0 ((2 * ABUF + 2 * BBUF) * 4)        // 37888 B
#define XS_STRIDE 132
#define GM_SMEM1 (128 * XS_STRIDE * 4)              // 67584 B

#define MMA_F16(d, a, b0, b1)                                               \
    asm volatile("mma.sync.aligned.m16n8k16.row.col.f32.f16.f16.f32 "       \
                 "{%0,%1,%2,%3}, {%4,%5,%6,%7}, {%8,%9}, {%0,%1,%2,%3};"    \
                 : "+f"(d[0]), "+f"(d[1]), "+f"(d[2]), "+f"(d[3])           \
                 : "r"(a[0]), "r"(a[1]), "r"(a[2]), "r"(a[3]),              \
                   "r"(b0), "r"(b1))

static __device__ __forceinline__ float gelu_f(float v) {
    float t = tanhf(0.7978845608028654f * (v + 0.044715f * v * v * v));
    return 0.5f * v * (1.0f + t);
}

template <int EPI>
__global__ __launch_bounds__(256)
void gemm_tc(const __half* __restrict__ A,
             const float* __restrict__ W,
             const float* __restrict__ bias,
             const float* __restrict__ res,
             void* __restrict__ Cv,
             const float* __restrict__ lng,
             const float* __restrict__ lnb,
             __half* __restrict__ Yh,
             int n, int M, int K) {
    extern __shared__ unsigned sm[];
    unsigned* As = sm;                  // 2 x ABUF
    unsigned* Bs = sm + 2 * ABUF;       // 2 x BBUF

    const int tid  = threadIdx.x;
    const int lane = tid & 31, warp = tid >> 5;
    const int lg = lane >> 2, lr = lane & 3;
    const int wm = warp & 3,  wn = warp >> 2;
    const int row0 = blockIdx.y * 128;
    const int col0 = blockIdx.x * 128;
    const int KT = K >> 5;

    float acc[2][8][4];
    #pragma unroll
    for (int mt = 0; mt < 2; mt++)
        #pragma unroll
        for (int nt = 0; nt < 8; nt++)
            #pragma unroll
            for (int i = 0; i < 4; i++) acc[mt][nt][i] = 0.f;

    uint2  rah[4];
    float4 rb0[2], rb1[2];

    // -------- prologue: load + store tile 0 --------
    #pragma unroll
    for (int j = 0; j < 4; j++) {
        int f = tid + j * 256;
        int r = f >> 3, kc = f & 7;
        uint2 v = make_uint2(0u, 0u);
        if (row0 + r < n)
            v = *(const uint2*)(A + (size_t)(row0 + r) * K + kc * 4);
        rah[j] = v;
    }
    #pragma unroll
    for (int j = 0; j < 2; j++) {
        int f = tid + j * 256;
        int ng = f & 31, k2 = f >> 5;
        rb0[j] = *(const float4*)(W + (size_t)(k2 * 2) * M + col0 + ng * 4);
        rb1[j] = *(const float4*)(W + (size_t)(k2 * 2 + 1) * M + col0 + ng * 4);
    }
    #pragma unroll
    for (int j = 0; j < 4; j++) {
        int f = tid + j * 256;
        int r = f >> 3, kc = f & 7;
        *(uint2*)(As + r * SA + kc * 2) = rah[j];
    }
    #pragma unroll
    for (int j = 0; j < 2; j++) {
        int f = tid + j * 256;
        int ng = f & 31, k2 = f >> 5;
        uint4 u;
        u.x = fh2(rb0[j].x, rb1[j].x);
        u.y = fh2(rb0[j].y, rb1[j].y);
        u.z = fh2(rb0[j].z, rb1[j].z);
        u.w = fh2(rb0[j].w, rb1[j].w);
        *(uint4*)(Bs + k2 * SB + ng * 4) = u;
    }
    __syncthreads();

    for (int kt = 0; kt < KT; kt++) {
        const int cur = kt & 1;
        if (kt + 1 < KT) {
            #pragma unroll
            for (int j = 0; j < 4; j++) {
                int f = tid + j * 256;
                int r = f >> 3, kc = f & 7;
                uint2 v = make_uint2(0u, 0u);
                if (row0 + r < n)
                    v = *(const uint2*)(A + (size_t)(row0 + r) * K + (kt + 1) * 32 + kc * 4);
                rah[j] = v;
            }
            #pragma unroll
            for (int j = 0; j < 2; j++) {
                int f = tid + j * 256;
                int ng = f & 31, k2 = f >> 5;
                int kr = (kt + 1) * 32 + k2 * 2;
                rb0[j] = *(const float4*)(W + (size_t)kr * M + col0 + ng * 4);
                rb1[j] = *(const float4*)(W + (size_t)(kr + 1) * M + col0 + ng * 4);
            }
        }
        const unsigned* Ab = As + cur * ABUF;
        const unsigned* Bb = Bs + cur * BBUF;
        #pragma unroll
        for (int ks = 0; ks < 2; ks++) {
            unsigned a[2][4];
            #pragma unroll
            for (int mt = 0; mt < 2; mt++) {
                const unsigned* ap = Ab + (wm * 32 + mt * 16 + lg) * SA + ks * 8 + lr;
                a[mt][0] = ap[0];
                a[mt][1] = ap[8 * SA];
                a[mt][2] = ap[4];
                a[mt][3] = ap[8 * SA + 4];
            }
            #pragma unroll
            for (int nt = 0; nt < 8; nt++) {
                const unsigned* bp = Bb + (ks * 8 + lr) * SB + wn * 64 + nt * 8 + lg;
                unsigned b0 = bp[0];
                unsigned b1 = bp[4 * SB];
                MMA_F16(acc[0][nt], a[0], b0, b1);
                MMA_F16(acc[1][nt], a[1], b0, b1);
            }
        }
        if (kt + 1 < KT) {
            unsigned* Ad = As + (cur ^ 1) * ABUF;
            unsigned* Bd = Bs + (cur ^ 1) * BBUF;
            #pragma unroll
            for (int j = 0; j < 4; j++) {
                int f = tid + j * 256;
                int r = f >> 3, kc = f & 7;
                *(uint2*)(Ad + r * SA + kc * 2) = rah[j];
            }
            #pragma unroll
            for (int j = 0; j < 2; j++) {
                int f = tid + j * 256;
                int ng = f & 31, k2 = f >> 5;
                uint4 u;
                u.x = fh2(rb0[j].x, rb1[j].x);
                u.y = fh2(rb0[j].y, rb1[j].y);
                u.z = fh2(rb0[j].z, rb1[j].z);
                u.w = fh2(rb0[j].w, rb1[j].w);
                *(uint4*)(Bd + k2 * SB + ng * 4) = u;
            }
        }
        __syncthreads();
    }

    const float sc = 0.08838834764831845f;  // D^-0.5
    if (EPI == 0) {
        #pragma unroll
        for (int mt = 0; mt < 2; mt++) {
            #pragma unroll
            for (int nt = 0; nt < 8; nt++) {
                int r = row0 + wm * 32 + mt * 16 + lg;
                int c = col0 + wn * 64 + nt * 8 + lr * 2;
                float b0 = bias[c], b1 = bias[c + 1];
                float v0 = acc[mt][nt][0] + b0;
                float v1 = acc[mt][nt][1] + b1;
                float v2 = acc[mt][nt][2] + b0;
                float v3 = acc[mt][nt][3] + b1;
                if (blockIdx.x == 0) {  // q columns
                    v0 *= sc; v1 *= sc; v2 *= sc; v3 *= sc;
                }
                __half* C = (__half*)Cv;
                if (r < n)
                    *(__half2*)(C + (size_t)r * M + c) = __floats2half2_rn(v0, v1);
                if (r + 8 < n)
                    *(__half2*)(C + (size_t)(r + 8) * M + c) = __floats2half2_rn(v2, v3);
            }
        }
    } else {
        // fused epilogue: x = acc + bias + res -> C (float) and smem xs;
        // then per-row LayerNorm over xs -> Yh (half). Requires M == 128.
        float* xs = (float*)sm;
        float* C = (float*)Cv;
        #pragma unroll
        for (int mt = 0; mt < 2; mt++) {
            #pragma unroll
            for (int nt = 0; nt < 8; nt++) {
                int rl = wm * 32 + mt * 16 + lg;
                int c  = wn * 64 + nt * 8 + lr * 2;
                int r  = row0 + rl;
                float b0 = bias[c], b1 = bias[c + 1];
                if (r < n) {
                    float2 rr = *(const float2*)(res + (size_t)r * M + c);
                    float2 o = make_float2(acc[mt][nt][0] + b0 + rr.x,
                                           acc[mt][nt][1] + b1 + rr.y);
                    *(float2*)(C + (size_t)r * M + c) = o;
                    xs[rl * XS_STRIDE + c] = o.x;
                    xs[rl * XS_STRIDE + c + 1] = o.y;
                }
                if (r + 8 < n) {
                    float2 rr = *(const float2*)(res + (size_t)(r + 8) * M + c);
                    float2 o = make_float2(acc[mt][nt][2] + b0 + rr.x,
                                           acc[mt][nt][3] + b1 + rr.y);
                    *(float2*)(C + (size_t)(r + 8) * M + c) = o;
                    xs[(rl + 8) * XS_STRIDE + c] = o.x;
                    xs[(rl + 8) * XS_STRIDE + c + 1] = o.y;
                }
            }
        }
        __syncthreads();
        float4 gg = ((const float4*)lng)[lane];
        float4 bb = ((const float4*)lnb)[lane];
        #pragma unroll
        for (int rr = 0; rr < 16; rr++) {
            int rl = warp * 16 + rr;
            int r  = row0 + rl;
            if (r >= n) break;
            float4 x = *(const float4*)(xs + rl * XS_STRIDE + lane * 4);
            float s  = x.x + x.y + x.z + x.w;
            float s2 = x.x * x.x + x.y * x.y + x.z * x.z + x.w * x.w;
            #pragma unroll
            for (int o = 16; o > 0; o >>= 1) {
                s  += __shfl_xor_sync(0xFFFFFFFFu, s,  o);
                s2 += __shfl_xor_sync(0xFFFFFFFFu, s2, o);
            }
            float mu  = s  * (1.0f / 128.0f);
            float var = s2 * (1.0f / 128.0f) - mu * mu;
            float rs  = rsqrtf(var + 1e-5f);
            float o0 = (x.x - mu) * rs * gg.x + bb.x;
            float o1 = (x.y - mu) * rs * gg.y + bb.y;
            float o2 = (x.z - mu) * rs * gg.z + bb.z;
            float o3 = (x.w - mu) * rs * gg.w + bb.w;
            *(uint2*)(Yh + (size_t)r * DDIM + lane * 4) =
                make_uint2(fh2(o0, o1), fh2(o2, o3));
        }
    }
}

// ---------------- fused MLP (fp16 in): out = res + gelu(Y@W1+b1)@W2 + b2 -----
#define SY 68                 // u32 stride for 128-half rows
#define YBUF (128 * SY)
#define FM_SMEM ((2 * YBUF + 2 * BBUF) * 4)  // 87040 B

__global__ __launch_bounds__(256)
void fmlp_kernel(const __half* __restrict__ Y,
                 const float* __restrict__ W1,
                 const float* __restrict__ b1,
                 const float* __restrict__ W2,
                 const float* __restrict__ b2,
                 const float* __restrict__ res,
                 float* __restrict__ C, int n) {
    extern __shared__ unsigned sm[];
    unsigned* Ys = sm;                 // 128 x SY
    unsigned* Hs = sm + YBUF;          // 128 x SY
    unsigned* Bs = sm + 2 * YBUF;      // 2 x BBUF

    const int tid  = threadIdx.x;
    const int lane = tid & 31, warp = tid >> 5;
    const int lg = lane >> 2, lr = lane & 3;
    const int wm = warp & 3,  wn = warp >> 2;
    const int row0 = blockIdx.x * 128;

    // stage Y tile (128 x 128 halves) zero-conversion
    #pragma unroll
    for (int j = 0; j < 16; j++) {
        int f = tid + j * 256;
        int r = f >> 5, c4 = f & 31;
        uint2 v = make_uint2(0u, 0u);
        if (row0 + r < n)
            v = *(const uint2*)(Y + (size_t)(row0 + r) * DDIM + c4 * 4);
        *(uint2*)(Ys + r * SY + c4 * 2) = v;
    }

    float acc2[2][8][4];
    #pragma unroll
    for (int mt = 0; mt < 2; mt++)
        #pragma unroll
        for (int nt = 0; nt < 8; nt++)
            #pragma unroll
            for (int i = 0; i < 4; i++) acc2[mt][nt][i] = 0.f;

    float4 rb0[2], rb1[2];
    __syncthreads();

    for (int cch = 0; cch < 4; cch++) {
        // ---- phase 1: H = Y @ W1[:, cch*128 .. +128] ----
        float acc[2][8][4];
        #pragma unroll
        for (int mt = 0; mt < 2; mt++)
            #pragma unroll
            for (int nt = 0; nt < 8; nt++)
                #pragma unroll
                for (int i = 0; i < 4; i++) acc[mt][nt][i] = 0.f;

        #pragma unroll
        for (int j = 0; j < 2; j++) {
            int f = tid + j * 256;
            int ng = f & 31, k2 = f >> 5;
            float4 w0 = *(const float4*)(W1 + (size_t)(k2 * 2) * 512 + cch * 128 + ng * 4);
            float4 w1 = *(const float4*)(W1 + (size_t)(k2 * 2 + 1) * 512 + cch * 128 + ng * 4);
            uint4 u;
            u.x = fh2(w0.x, w1.x); u.y = fh2(w0.y, w1.y);
            u.z = fh2(w0.z, w1.z); u.w = fh2(w0.w, w1.w);
            *(uint4*)(Bs + k2 * SB + ng * 4) = u;
        }
        __syncthreads();

        #pragma unroll
        for (int kt = 0; kt < 4; kt++) {
            const int cur = kt & 1;
            if (kt < 3) {
                #pragma unroll
                for (int j = 0; j < 2; j++) {
                    int f = tid + j * 256;
                    int ng = f & 31, k2 = f >> 5;
                    int kr = (kt + 1) * 32 + k2 * 2;
                    rb0[j] = *(const float4*)(W1 + (size_t)kr * 512 + cch * 128 + ng * 4);
                    rb1[j] = *(const float4*)(W1 + (size_t)(kr + 1) * 512 + cch * 128 + ng * 4);
                }
            }
            const unsigned* Bb = Bs + cur * BBUF;
            #pragma unroll
            for (int ks = 0; ks < 2; ks++) {
                unsigned a[2][4];
                #pragma unroll
                for (int mt = 0; mt < 2; mt++) {
                    const unsigned* ap = Ys + (wm * 32 + mt * 16 + lg) * SY + (kt * 2 + ks) * 8 + lr;
                    a[mt][0] = ap[0];
                    a[mt][1] = ap[8 * SY];
                    a[mt][2] = ap[4];
                    a[mt][3] = ap[8 * SY + 4];
                }
                #pragma unroll
                for (int nt = 0; nt < 8; nt++) {
                    const unsigned* bp = Bb + (ks * 8 + lr) * SB + wn * 64 + nt * 8 + lg;
                    unsigned b0 = bp[0];
                    unsigned b1v = bp[4 * SB];
                    MMA_F16(acc[0][nt], a[0], b0, b1v);
                    MMA_F16(acc[1][nt], a[1], b0, b1v);
                }
            }
            if (kt < 3) {
                unsigned* Bd = Bs + (cur ^ 1) * BBUF;
                #pragma unroll
                for (int j = 0; j < 2; j++) {
                    int f = tid + j * 256;
                    int ng = f & 31, k2 = f >> 5;
                    uint4 u;
                    u.x = fh2(rb0[j].x, rb1[j].x); u.y = fh2(rb0[j].y, rb1[j].y);
                    u.z = fh2(rb0[j].z, rb1[j].z); u.w = fh2(rb0[j].w, rb1[j].w);
                    *(uint4*)(Bd + k2 * SB + ng * 4) = u;
                }
            }
            __syncthreads();
        }

        // gelu + b1 -> Hs (fp16)
        #pragma unroll
        for (int mt = 0; mt < 2; mt++) {
            #pragma unroll
            for (int nt = 0; nt < 8; nt++) {
                int rloc = wm * 32 + mt * 16 + lg;
                int cu = wn * 32 + nt * 4 + lr;   // u32 column index
                float bb0 = b1[cch * 128 + cu * 2];
                float bb1 = b1[cch * 128 + cu * 2 + 1];
                Hs[rloc * SY + cu] =
                    fh2(gelu_f(acc[mt][nt][0] + bb0), gelu_f(acc[mt][nt][1] + bb1));
                Hs[(rloc + 8) * SY + cu] =
                    fh2(gelu_f(acc[mt][nt][2] + bb0), gelu_f(acc[mt][nt][3] + bb1));
            }
        }
        __syncthreads();

        // ---- phase 2: acc2 += H @ W2[cch*128 .. +128, :] ----
        #pragma unroll
        for (int j = 0; j < 2; j++) {
            int f = tid + j * 256;
            int ng = f & 31, k2 = f >> 5;
            float4 w0 = *(const float4*)(W2 + (size_t)(cch * 128 + k2 * 2) * DDIM + ng * 4);
            float4 w1 = *(const float4*)(W2 + (size_t)(cch * 128 + k2 * 2 + 1) * DDIM + ng * 4);
            uint4 u;
            u.x = fh2(w0.x, w1.x); u.y = fh2(w0.y, w1.y);
            u.z = fh2(w0.z, w1.z); u.w = fh2(w0.w, w1.w);
            *(uint4*)(Bs + k2 * SB + ng * 4) = u;
        }
        __syncthreads();

        #pragma unroll
        for (int kt = 0; kt < 4; kt++) {
            const int cur = kt & 1;
            if (kt < 3) {
                #pragma unroll
                for (int j = 0; j < 2; j++) {
                    int f = tid + j * 256;
                    int ng = f & 31, k2 = f >> 5;
                    int kr = cch * 128 + (kt + 1) * 32 + k2 * 2;
                    rb0[j] = *(const float4*)(W2 + (size_t)kr * DDIM + ng * 4);
                    rb1[j] = *(const float4*)(W2 + (size_t)(kr + 1) * DDIM + ng * 4);
                }
            }
            const unsigned* Bb = Bs + cur * BBUF;
            #pragma unroll
            for (int ks = 0; ks < 2; ks++) {
                unsigned a[2][4];
                #pragma unroll
                for (int mt = 0; mt < 2; mt++) {
                    const unsigned* ap = Hs + (wm * 32 + mt * 16 + lg) * SY + (kt * 2 + ks) * 8 + lr;
                    a[mt][0] = ap[0];
                    a[mt][1] = ap[8 * SY];
                    a[mt][2] = ap[4];
                    a[mt][3] = ap[8 * SY + 4];
                }
                #pragma unroll
                for (int nt = 0; nt < 8; nt++) {
                    const unsigned* bp = Bb + (ks * 8 + lr) * SB + wn * 64 + nt * 8 + lg;
                    unsigned b0 = bp[0];
                    unsigned b1v = bp[4 * SB];
                    MMA_F16(acc2[0][nt], a[0], b0, b1v);
                    MMA_F16(acc2[1][nt], a[1], b0, b1v);
                }
            }
            if (kt < 3) {
                unsigned* Bd = Bs + (cur ^ 1) * BBUF;
                #pragma unroll
                for (int j = 0; j < 2; j++) {
                    int f = tid + j * 256;
                    int ng = f & 31, k2 = f >> 5;
                    uint4 u;
                    u.x = fh2(rb0[j].x, rb1[j].x); u.y = fh2(rb0[j].y, rb1[j].y);
                    u.z = fh2(rb0[j].z, rb1[j].z); u.w = fh2(rb0[j].w, rb1[j].w);
                    *(uint4*)(Bd + k2 * SB + ng * 4) = u;
                }
            }
            __syncthreads();
        }
    }

    // epilogue: + b2 + res
    #pragma unroll
    for (int mt = 0; mt < 2; mt++) {
        #pragma unroll
        for (int nt = 0; nt < 8; nt++) {
            int r = row0 + wm * 32 + mt * 16 + lg;
            int c = wn * 64 + nt * 8 + lr * 2;
            float bb0 = b2[c], bb1 = b2[c + 1];
            if (r < n) {
                float2 rr = *(const float2*)(res + (size_t)r * DDIM + c);
                *(float2*)(C + (size_t)r * DDIM + c) =
                    make_float2(acc2[mt][nt][0] + bb0 + rr.x,
                                acc2[mt][nt][1] + bb1 + rr.y);
            }
            if (r + 8 < n) {
                float2 rr = *(const float2*)(res + (size_t)(r + 8) * DDIM + c);
                *(float2*)(C + (size_t)(r + 8) * DDIM + c) =
                    make_float2(acc2[mt][nt][2] + bb0 + rr.x,
                                acc2[mt][nt][3] + bb1 + rr.y);
            }
        }
    }
}

// ---------------- launch ----------------
extern "C" void kernel_launch(void* const* d_in, const int* in_sizes, int n_in,
                              void* d_out, int out_size) {
    const float* node_feature = (const float*)d_in[0];
    const float* dist_attn    = (const float*)d_in[1];
    const float* path_attn    = (const float*)d_in[2];
    const int*   src          = (const int*)d_in[3];
    const int*   dst          = (const int*)d_in[4];
    const float* ln1_g        = (const float*)d_in[5];
    const float* ln1_b        = (const float*)d_in[6];
    const float* qkv_w        = (const float*)d_in[7];
    const float* qkv_b        = (const float*)d_in[8];
    const float* in_proj_w    = (const float*)d_in[9];
    const float* in_proj_b    = (const float*)d_in[10];
    const float* res_ln_g     = (const float*)d_in[11];
    const float* res_ln_b     = (const float*)d_in[12];
    const float* mlp_w1       = (const float*)d_in[13];
    const float* mlp_b1       = (const float*)d_in[14];
    const float* mlp_w2       = (const float*)d_in[15];
    const float* mlp_b2       = (const float*)d_in[16];
    float* out = (float*)d_out;

    cudaFuncSetAttribute(gemm_tc<0>, cudaFuncAttributeMaxDynamicSharedMemorySize, GM_SMEM0);
    cudaFuncSetAttribute(gemm_tc<1>, cudaFuncAttributeMaxDynamicSharedMemorySize, GM_SMEM1);
    cudaFuncSetAttribute(fmlp_kernel, cudaFuncAttributeMaxDynamicSharedMemorySize, FM_SMEM);

    void* p;
    cudaGetSymbolAddress(&p, g_h);    float*  ph   = (float*)p;
    cudaGetSymbolAddress(&p, g_hh);   __half* phh  = (__half*)p;
    cudaGetSymbolAddress(&p, g_qkv);  __half* pqkv = (__half*)p;
    cudaGetSymbolAddress(&p, g_agg);  __half* pagg = (__half*)p;
    cudaGetSymbolAddress(&p, g_x);    float*  px   = (float*)p;
    cudaGetSymbolAddress(&p, g_yh);   __half* pyh  = (__half*)p;

    const int RB = (NN + 127) / 128;           // 391 row blocks
    const int LN_BLOCKS = (NN + 7) / 8;
    const int E_BLOCKS  = (EE + 255) / 256;
    const int ATTN_BLOCKS = (NN * 32 + 255) / 256;

    // CSR build (+ precompute of src & dist+path in CSR order)
    zero_ln_kernel<<<NBLK + LN_BLOCKS, 256>>>(node_feature, ln1_g, ln1_b, ph, phh);
    hist_kernel<<<E_BLOCKS, 256>>>(dst);
    scanA_kernel<<<NB, 256>>>();
    scanBC_kernel<<<NB, 256>>>();
    scatter_kernel<<<E_BLOCKS, 256>>>(src, dst, dist_attn, path_attn);

    // main pipeline
    gemm_tc<0><<<dim3(3, RB), 256, GM_SMEM0>>>(phh, qkv_w, qkv_b, nullptr, pqkv,
                                               nullptr, nullptr, nullptr, NN, 384, 128);
    attn_kernel<<<ATTN_BLOCKS, 256>>>();
    gemm_tc<1><<<dim3(1, RB), 256, GM_SMEM1>>>(pagg, in_proj_w, in_proj_b, ph, px,
                                               res_ln_g, res_ln_b, pyh, NN, 128, 128);
    fmlp_kernel<<<RB, 256, FM_SMEM>>>(pyh, mlp_w1, mlp_b1, mlp_w2, mlp_b2, px, out, NN);
}

// round 16
// speedup vs baseline: 1.1000x; 1.1000x over previous
#include <cuda_runtime.h>
#include <cuda_fp16.h>
#include <math.h>

#define NN 50000
#define EE 600000
#define DDIM 128
#define HH 8
#define NB 196   // ceil(NN/256) scan blocks
#define NBLK 196 // N_BLOCKS == NB

// ---------------- scratch (static device memory; no allocs) ----------------
static __device__ float  g_h[NN * DDIM];           // LN1 output (float, residual)
static __device__ __half g_hh[NN * DDIM];          // LN1 output (half, GEMM A)
static __device__ __half g_qkv[NN * 3 * DDIM];     // [N][3][H][16] half
static __device__ __half g_agg[NN * DDIM];         // aggregated msgs (half)
static __device__ float  g_x[NN * DDIM];           // residual stream
static __device__ __half g_yh[NN * DDIM];          // LN2 output (half)
static __device__ int    g_deg[NN];
static __device__ int    g_off[NN + 1];
static __device__ int    g_pos[NN];
static __device__ int    g_esrc[EE];               // src node per CSR slot
static __device__ float  g_edp[EE * HH];           // dist+path per CSR slot
static __device__ int    g_bsum[NB];

// ---------------- half pack/unpack helpers ----------------
static __device__ __forceinline__ unsigned fh2(float lo, float hi) {
    __half2 hv = __floats2half2_rn(lo, hi);
    return *reinterpret_cast<unsigned*>(&hv);
}
static __device__ __forceinline__ void ldh8(const __half* p, float* o) {
    uint4 u = *(const uint4*)p;
    __half2* hp = (__half2*)&u;
    #pragma unroll
    for (int j = 0; j < 4; j++) {
        float2 f = __half22float2(hp[j]);
        o[2 * j] = f.x; o[2 * j + 1] = f.y;
    }
}

// ---------------- CSR build ----------------
__global__ void hist_kernel(const int* __restrict__ dst) {
    int e = blockIdx.x * blockDim.x + threadIdx.x;
    if (e < EE) atomicAdd(&g_deg[dst[e]], 1);
}
__global__ void scanA_kernel() {
    __shared__ int sh[256];
    int t = threadIdx.x;
    int i = blockIdx.x * 256 + t;
    int val = (i < NN) ? g_deg[i] : 0;
    sh[t] = val;
    #pragma unroll
    for (int o = 1; o < 256; o <<= 1) {
        __syncthreads();
        int x = (t >= o) ? sh[t - o] : 0;
        __syncthreads();
        sh[t] += x;
    }
    __syncthreads();
    int excl = sh[t] - val;
    if (i < NN) g_off[i] = excl;
    if (t == 255) g_bsum[blockIdx.x] = sh[255];
}
__global__ void scanBC_kernel() {
    __shared__ int sh[256];
    int t = threadIdx.x;
    sh[t] = (t < blockIdx.x && t < NB) ? g_bsum[t] : 0;
    __syncthreads();
    #pragma unroll
    for (int o = 128; o > 0; o >>= 1) {
        if (t < o) sh[t] += sh[t + o];
        __syncthreads();
    }
    int base = sh[0];
    int i = blockIdx.x * 256 + t;
    if (i < NN) {
        int v = g_off[i] + base;
        g_off[i] = v;
        g_pos[i] = v;
    }
    if (i == 0) g_off[NN] = EE;
}
__global__ void scatter_kernel(const int* __restrict__ src,
                               const int* __restrict__ dst,
                               const float* __restrict__ dist,
                               const float* __restrict__ path) {
    int e = blockIdx.x * blockDim.x + threadIdx.x;
    if (e >= EE) return;
    int d = dst[e];
    int p = atomicAdd(&g_pos[d], 1);
    g_esrc[p] = src[e];
    float4 d0 = *(const float4*)(dist + (size_t)e * 8);
    float4 d1 = *(const float4*)(dist + (size_t)e * 8 + 4);
    float4 p0 = *(const float4*)(path + (size_t)e * 8);
    float4 p1 = *(const float4*)(path + (size_t)e * 8 + 4);
    *(float4*)(g_edp + (size_t)p * 8) =
        make_float4(d0.x + p0.x, d0.y + p0.y, d0.z + p0.z, d0.w + p0.w);
    *(float4*)(g_edp + (size_t)p * 8 + 4) =
        make_float4(d1.x + p1.x, d1.y + p1.y, d1.z + p1.z, d1.w + p1.w);
}

// ---------------- merged zero_deg + LN1 ----------------
__global__ void zero_ln_kernel(const float* __restrict__ in,
                               const float* __restrict__ g,
                               const float* __restrict__ b,
                               float* __restrict__ outf,
                               __half* __restrict__ outh) {
    if (blockIdx.x < NBLK) {
        int i = blockIdx.x * 256 + threadIdx.x;
        if (i < NN) g_deg[i] = 0;
        return;
    }
    int wid  = ((blockIdx.x - NBLK) * 256 + threadIdx.x) >> 5;
    int lane = threadIdx.x & 31;
    if (wid >= NN) return;
    const float4* row = (const float4*)(in + (size_t)wid * DDIM);
    float4 x = row[lane];
    float s  = x.x + x.y + x.z + x.w;
    float s2 = x.x * x.x + x.y * x.y + x.z * x.z + x.w * x.w;
    #pragma unroll
    for (int o = 16; o > 0; o >>= 1) {
        s  += __shfl_xor_sync(0xFFFFFFFFu, s,  o);
        s2 += __shfl_xor_sync(0xFFFFFFFFu, s2, o);
    }
    float mu  = s  * (1.0f / 128.0f);
    float var = s2 * (1.0f / 128.0f) - mu * mu;
    float r   = rsqrtf(var + 1e-5f);
    float4 gg = ((const float4*)g)[lane];
    float4 bb = ((const float4*)b)[lane];
    float4 o4;
    o4.x = (x.x - mu) * r * gg.x + bb.x;
    o4.y = (x.y - mu) * r * gg.y + bb.y;
    o4.z = (x.z - mu) * r * gg.z + bb.z;
    o4.w = (x.w - mu) * r * gg.w + bb.w;
    ((float4*)(outf + (size_t)wid * DDIM))[lane] = o4;
    *(uint2*)(outh + (size_t)wid * DDIM + lane * 4) =
        make_uint2(fh2(o4.x, o4.y), fh2(o4.z, o4.w));
}

// ---------------- fused attention: warp = dst, 2 edges x 2-deep pipeline ----
// (R14-proven version: ~64 regs, full occupancy)
#define ALOAD2(s, i) do {                                                   \
    int off_ = gho + ((i) << 1);                                            \
    int idx_ = beg + (off_ < cnt ? off_ : cnt - 1);                         \
    int s_ = g_esrc[idx_];                                                  \
    ldh8(g_qkv + (size_t)s_ * 384 + l16 * 8, q##s);                         \
    ldh8(g_qkv + (size_t)s_ * 384 + 256 + l16 * 8, v##s);                   \
    dp##s = (off_ < cnt) ? g_edp[(size_t)idx_ * 8 + h2] : -1e38f;           \
} while (0)

#define ASTEP2(s) do {                                                      \
    float p_ = q##s[0] * kv[0] + q##s[1] * kv[1] + q##s[2] * kv[2]          \
             + q##s[3] * kv[3] + q##s[4] * kv[4] + q##s[5] * kv[5]          \
             + q##s[6] * kv[6] + q##s[7] * kv[7];                           \
    float dot_ = p_ + __shfl_xor_sync(0xFFFFFFFFu, p_, 1);                  \
    float a_ = dot_ + dp##s;                                                \
    float mn_ = fmaxf(m, a_);                                               \
    float corr_ = __expf(m - mn_);                                          \
    float pw_ = __expf(a_ - mn_);                                           \
    den = den * corr_ + pw_;                                                \
    _Pragma("unroll")                                                       \
    for (int j_ = 0; j_ < 8; j_++)                                          \
        acc[j_] = acc[j_] * corr_ + v##s[j_] * pw_;                         \
    m = mn_;                                                                \
} while (0)

__global__ void attn_kernel() {
    int w = (blockIdx.x * blockDim.x + threadIdx.x) >> 5;
    if (w >= NN) return;
    int lane = threadIdx.x & 31;
    int gho = lane >> 4;     // half-warp id (edge parity)
    int l16 = lane & 15;     // lane within half: dims [l16*8, l16*8+8)
    int h2  = l16 >> 1;      // head
    int beg = g_off[w], end = g_off[w + 1];
    int cnt = end - beg;     // warp-uniform
    float kv[8];
    ldh8(g_qkv + (size_t)w * 384 + 128 + l16 * 8, kv);
    float acc[8];
    #pragma unroll
    for (int j = 0; j < 8; j++) acc[j] = 0.f;
    float m = -1e30f, den = 0.f;

    int steps = (cnt + 1) >> 1;   // warp-uniform iteration count
    if (steps > 0) {
        float q0[8], v0[8], q1[8], v1[8];
        float dp0 = 0.f, dp1 = 0.f;
        ALOAD2(0, 0);
        if (steps > 1) ALOAD2(1, 1);
        int i = 0;
        while (i + 2 <= steps) {
            ASTEP2(0);
            if (i + 2 < steps) ALOAD2(0, i + 2);
            ASTEP2(1);
            if (i + 3 < steps) ALOAD2(1, i + 3);
            i += 2;
        }
        if (i < steps) ASTEP2(0);
    }

    // merge the two half-warp softmax states (exact)
    float mo  = __shfl_xor_sync(0xFFFFFFFFu, m, 16);
    float dno = __shfl_xor_sync(0xFFFFFFFFu, den, 16);
    float mn  = fmaxf(m, mo);
    float cs  = __expf(m - mn);
    float co  = __expf(mo - mn);
    float dtot = den * cs + dno * co;
    #pragma unroll
    for (int j = 0; j < 8; j++) {
        float ao = __shfl_xor_sync(0xFFFFFFFFu, acc[j], 16);
        acc[j] = acc[j] * cs + ao * co;
    }
    float inv = (dtot > 0.f) ? (1.0f / dtot) : 0.f;
    if (gho == 0) {
        uint4 o;
        o.x = fh2(acc[0] * inv, acc[1] * inv);
        o.y = fh2(acc[2] * inv, acc[3] * inv);
        o.z = fh2(acc[4] * inv, acc[5] * inv);
        o.w = fh2(acc[6] * inv, acc[7] * inv);
        *(uint4*)(g_agg + (size_t)w * DDIM + l16 * 8) = o;
    }
}

// ---------------- FP16 tensor-core GEMM (m16n8k16, fp32 accum) ----------------
// EPI==0 (qkv): writes half C, q-scale on col-block 0.
// EPI==1 (in_proj): writes float C = acc+bias+res AND fused LayerNorm -> Yh.
#define SA 20
#define SB 136
#define ABUF (128 * SA)   // 2560 u32
#define BBUF (16 * SB)    // 2176 u32
#define GM_SMEM0 ((2 * ABUF + 2 * BBUF) * 4)        // 37888 B
#define XS_STRIDE 132
#define GM_SMEM1 (128 * XS_STRIDE * 4)              // 67584 B

#define MMA_F16(d, a, b0, b1)                                               \
    asm volatile("mma.sync.aligned.m16n8k16.row.col.f32.f16.f16.f32 "       \
                 "{%0,%1,%2,%3}, {%4,%5,%6,%7}, {%8,%9}, {%0,%1,%2,%3};"    \
                 : "+f"(d[0]), "+f"(d[1]), "+f"(d[2]), "+f"(d[3])           \
                 : "r"(a[0]), "r"(a[1]), "r"(a[2]), "r"(a[3]),              \
                   "r"(b0), "r"(b1))

static __device__ __forceinline__ float gelu_f(float v) {
    float t = tanhf(0.7978845608028654f * (v + 0.044715f * v * v * v));
    return 0.5f * v * (1.0f + t);
}

template <int EPI>
__global__ __launch_bounds__(256)
void gemm_tc(const __half* __restrict__ A,
             const float* __restrict__ W,
             const float* __restrict__ bias,
             const float* __restrict__ res,
             void* __restrict__ Cv,
             const float* __restrict__ lng,
             const float* __restrict__ lnb,
             __half* __restrict__ Yh,
             int n, int M, int K) {
    extern __shared__ unsigned sm[];
    unsigned* As = sm;                  // 2 x ABUF
    unsigned* Bs = sm + 2 * ABUF;       // 2 x BBUF

    const int tid  = threadIdx.x;
    const int lane = tid & 31, warp = tid >> 5;
    const int lg = lane >> 2, lr = lane & 3;
    const int wm = warp & 3,  wn = warp >> 2;
    const int row0 = blockIdx.y * 128;
    const int col0 = blockIdx.x * 128;
    const int KT = K >> 5;

    float acc[2][8][4];
    #pragma unroll
    for (int mt = 0; mt < 2; mt++)
        #pragma unroll
        for (int nt = 0; nt < 8; nt++)
            #pragma unroll
            for (int i = 0; i < 4; i++) acc[mt][nt][i] = 0.f;

    uint2  rah[4];
    float4 rb0[2], rb1[2];

    // -------- prologue: load + store tile 0 --------
    #pragma unroll
    for (int j = 0; j < 4; j++) {
        int f = tid + j * 256;
        int r = f >> 3, kc = f & 7;
        uint2 v = make_uint2(0u, 0u);
        if (row0 + r < n)
            v = *(const uint2*)(A + (size_t)(row0 + r) * K + kc * 4);
        rah[j] = v;
    }
    #pragma unroll
    for (int j = 0; j < 2; j++) {
        int f = tid + j * 256;
        int ng = f & 31, k2 = f >> 5;
        rb0[j] = *(const float4*)(W + (size_t)(k2 * 2) * M + col0 + ng * 4);
        rb1[j] = *(const float4*)(W + (size_t)(k2 * 2 + 1) * M + col0 + ng * 4);
    }
    #pragma unroll
    for (int j = 0; j < 4; j++) {
        int f = tid + j * 256;
        int r = f >> 3, kc = f & 7;
        *(uint2*)(As + r * SA + kc * 2) = rah[j];
    }
    #pragma unroll
    for (int j = 0; j < 2; j++) {
        int f = tid + j * 256;
        int ng = f & 31, k2 = f >> 5;
        uint4 u;
        u.x = fh2(rb0[j].x, rb1[j].x);
        u.y = fh2(rb0[j].y, rb1[j].y);
        u.z = fh2(rb0[j].z, rb1[j].z);
        u.w = fh2(rb0[j].w, rb1[j].w);
        *(uint4*)(Bs + k2 * SB + ng * 4) = u;
    }
    __syncthreads();

    for (int kt = 0; kt < KT; kt++) {
        const int cur = kt & 1;
        if (kt + 1 < KT) {
            #pragma unroll
            for (int j = 0; j < 4; j++) {
                int f = tid + j * 256;
                int r = f >> 3, kc = f & 7;
                uint2 v = make_uint2(0u, 0u);
                if (row0 + r < n)
                    v = *(const uint2*)(A + (size_t)(row0 + r) * K + (kt + 1) * 32 + kc * 4);
                rah[j] = v;
            }
            #pragma unroll
            for (int j = 0; j < 2; j++) {
                int f = tid + j * 256;
                int ng = f & 31, k2 = f >> 5;
                int kr = (kt + 1) * 32 + k2 * 2;
                rb0[j] = *(const float4*)(W + (size_t)kr * M + col0 + ng * 4);
                rb1[j] = *(const float4*)(W + (size_t)(kr + 1) * M + col0 + ng * 4);
            }
        }
        const unsigned* Ab = As + cur * ABUF;
        const unsigned* Bb = Bs + cur * BBUF;
        #pragma unroll
        for (int ks = 0; ks < 2; ks++) {
            unsigned a[2][4];
            #pragma unroll
            for (int mt = 0; mt < 2; mt++) {
                const unsigned* ap = Ab + (wm * 32 + mt * 16 + lg) * SA + ks * 8 + lr;
                a[mt][0] = ap[0];
                a[mt][1] = ap[8 * SA];
                a[mt][2] = ap[4];
                a[mt][3] = ap[8 * SA + 4];
            }
            #pragma unroll
            for (int nt = 0; nt < 8; nt++) {
                const unsigned* bp = Bb + (ks * 8 + lr) * SB + wn * 64 + nt * 8 + lg;
                unsigned b0 = bp[0];
                unsigned b1 = bp[4 * SB];
                MMA_F16(acc[0][nt], a[0], b0, b1);
                MMA_F16(acc[1][nt], a[1], b0, b1);
            }
        }
        if (kt + 1 < KT) {
            unsigned* Ad = As + (cur ^ 1) * ABUF;
            unsigned* Bd = Bs + (cur ^ 1) * BBUF;
            #pragma unroll
            for (int j = 0; j < 4; j++) {
                int f = tid + j * 256;
                int r = f >> 3, kc = f & 7;
                *(uint2*)(Ad + r * SA + kc * 2) = rah[j];
            }
            #pragma unroll
            for (int j = 0; j < 2; j++) {
                int f = tid + j * 256;
                int ng = f & 31, k2 = f >> 5;
                uint4 u;
                u.x = fh2(rb0[j].x, rb1[j].x);
                u.y = fh2(rb0[j].y, rb1[j].y);
                u.z = fh2(rb0[j].z, rb1[j].z);
                u.w = fh2(rb0[j].w, rb1[j].w);
                *(uint4*)(Bd + k2 * SB + ng * 4) = u;
            }
        }
        __syncthreads();
    }

    const float sc = 0.08838834764831845f;  // D^-0.5
    if (EPI == 0) {
        #pragma unroll
        for (int mt = 0; mt < 2; mt++) {
            #pragma unroll
            for (int nt = 0; nt < 8; nt++) {
                int r = row0 + wm * 32 + mt * 16 + lg;
                int c = col0 + wn * 64 + nt * 8 + lr * 2;
                float b0 = bias[c], b1 = bias[c + 1];
                float v0 = acc[mt][nt][0] + b0;
                float v1 = acc[mt][nt][1] + b1;
                float v2 = acc[mt][nt][2] + b0;
                float v3 = acc[mt][nt][3] + b1;
                if (blockIdx.x == 0) {  // q columns
                    v0 *= sc; v1 *= sc; v2 *= sc; v3 *= sc;
                }
                __half* C = (__half*)Cv;
                if (r < n)
                    *(__half2*)(C + (size_t)r * M + c) = __floats2half2_rn(v0, v1);
                if (r + 8 < n)
                    *(__half2*)(C + (size_t)(r + 8) * M + c) = __floats2half2_rn(v2, v3);
            }
        }
    } else {
        // fused epilogue: x = acc + bias + res -> C (float) and smem xs;
        // then per-row LayerNorm over xs -> Yh (half). Requires M == 128.
        float* xs = (float*)sm;
        float* C = (float*)Cv;
        #pragma unroll
        for (int mt = 0; mt < 2; mt++) {
            #pragma unroll
            for (int nt = 0; nt < 8; nt++) {
                int rl = wm * 32 + mt * 16 + lg;
                int c  = wn * 64 + nt * 8 + lr * 2;
                int r  = row0 + rl;
                float b0 = bias[c], b1 = bias[c + 1];
                if (r < n) {
                    float2 rr = *(const float2*)(res + (size_t)r * M + c);
                    float2 o = make_float2(acc[mt][nt][0] + b0 + rr.x,
                                           acc[mt][nt][1] + b1 + rr.y);
                    *(float2*)(C + (size_t)r * M + c) = o;
                    xs[rl * XS_STRIDE + c] = o.x;
                    xs[rl * XS_STRIDE + c + 1] = o.y;
                }
                if (r + 8 < n) {
                    float2 rr = *(const float2*)(res + (size_t)(r + 8) * M + c);
                    float2 o = make_float2(acc[mt][nt][2] + b0 + rr.x,
                                           acc[mt][nt][3] + b1 + rr.y);
                    *(float2*)(C + (size_t)(r + 8) * M + c) = o;
                    xs[(rl + 8) * XS_STRIDE + c] = o.x;
                    xs[(rl + 8) * XS_STRIDE + c + 1] = o.y;
                }
            }
        }
        __syncthreads();
        float4 gg = ((const float4*)lng)[lane];
        float4 bb = ((const float4*)lnb)[lane];
        #pragma unroll
        for (int rr = 0; rr < 16; rr++) {
            int rl = warp * 16 + rr;
            int r  = row0 + rl;
            if (r >= n) break;
            float4 x = *(const float4*)(xs + rl * XS_STRIDE + lane * 4);
            float s  = x.x + x.y + x.z + x.w;
            float s2 = x.x * x.x + x.y * x.y + x.z * x.z + x.w * x.w;
            #pragma unroll
            for (int o = 16; o > 0; o >>= 1) {
                s  += __shfl_xor_sync(0xFFFFFFFFu, s,  o);
                s2 += __shfl_xor_sync(0xFFFFFFFFu, s2, o);
            }
            float mu  = s  * (1.0f / 128.0f);
            float var = s2 * (1.0f / 128.0f) - mu * mu;
            float rs  = rsqrtf(var + 1e-5f);
            float o0 = (x.x - mu) * rs * gg.x + bb.x;
            float o1 = (x.y - mu) * rs * gg.y + bb.y;
            float o2 = (x.z - mu) * rs * gg.z + bb.z;
            float o3 = (x.w - mu) * rs * gg.w + bb.w;
            *(uint2*)(Yh + (size_t)r * DDIM + lane * 4) =
                make_uint2(fh2(o0, o1), fh2(o2, o3));
        }
    }
}

// ---------------- fused MLP (fp16 in): out = res + gelu(Y@W1+b1)@W2 + b2 -----
#define SY 68                 // u32 stride for 128-half rows
#define YBUF (128 * SY)
#define FM_SMEM ((2 * YBUF + 2 * BBUF) * 4)  // 87040 B

__global__ __launch_bounds__(256)
void fmlp_kernel(const __half* __restrict__ Y,
                 const float* __restrict__ W1,
                 const float* __restrict__ b1,
                 const float* __restrict__ W2,
                 const float* __restrict__ b2,
                 const float* __restrict__ res,
                 float* __restrict__ C, int n) {
    extern __shared__ unsigned sm[];
    unsigned* Ys = sm;                 // 128 x SY
    unsigned* Hs = sm + YBUF;          // 128 x SY
    unsigned* Bs = sm + 2 * YBUF;      // 2 x BBUF

    const int tid  = threadIdx.x;
    const int lane = tid & 31, warp = tid >> 5;
    const int lg = lane >> 2, lr = lane & 3;
    const int wm = warp & 3,  wn = warp >> 2;
    const int row0 = blockIdx.x * 128;

    // stage Y tile (128 x 128 halves) zero-conversion
    #pragma unroll
    for (int j = 0; j < 16; j++) {
        int f = tid + j * 256;
        int r = f >> 5, c4 = f & 31;
        uint2 v = make_uint2(0u, 0u);
        if (row0 + r < n)
            v = *(const uint2*)(Y + (size_t)(row0 + r) * DDIM + c4 * 4);
        *(uint2*)(Ys + r * SY + c4 * 2) = v;
    }

    float acc2[2][8][4];
    #pragma unroll
    for (int mt = 0; mt < 2; mt++)
        #pragma unroll
        for (int nt = 0; nt < 8; nt++)
            #pragma unroll
            for (int i = 0; i < 4; i++) acc2[mt][nt][i] = 0.f;

    float4 rb0[2], rb1[2];
    __syncthreads();

    for (int cch = 0; cch < 4; cch++) {
        // ---- phase 1: H = Y @ W1[:, cch*128 .. +128] ----
        float acc[2][8][4];
        #pragma unroll
        for (int mt = 0; mt < 2; mt++)
            #pragma unroll
            for (int nt = 0; nt < 8; nt++)
                #pragma unroll
                for (int i = 0; i < 4; i++) acc[mt][nt][i] = 0.f;

        #pragma unroll
        for (int j = 0; j < 2; j++) {
            int f = tid + j * 256;
            int ng = f & 31, k2 = f >> 5;
            float4 w0 = *(const float4*)(W1 + (size_t)(k2 * 2) * 512 + cch * 128 + ng * 4);
            float4 w1 = *(const float4*)(W1 + (size_t)(k2 * 2 + 1) * 512 + cch * 128 + ng * 4);
            uint4 u;
            u.x = fh2(w0.x, w1.x); u.y = fh2(w0.y, w1.y);
            u.z = fh2(w0.z, w1.z); u.w = fh2(w0.w, w1.w);
            *(uint4*)(Bs + k2 * SB + ng * 4) = u;
        }
        __syncthreads();

        #pragma unroll
        for (int kt = 0; kt < 4; kt++) {
            const int cur = kt & 1;
            if (kt < 3) {
                #pragma unroll
                for (int j = 0; j < 2; j++) {
                    int f = tid + j * 256;
                    int ng = f & 31, k2 = f >> 5;
                    int kr = (kt + 1) * 32 + k2 * 2;
                    rb0[j] = *(const float4*)(W1 + (size_t)kr * 512 + cch * 128 + ng * 4);
                    rb1[j] = *(const float4*)(W1 + (size_t)(kr + 1) * 512 + cch * 128 + ng * 4);
                }
            }
            const unsigned* Bb = Bs + cur * BBUF;
            #pragma unroll
            for (int ks = 0; ks < 2; ks++) {
                unsigned a[2][4];
                #pragma unroll
                for (int mt = 0; mt < 2; mt++) {
                    const unsigned* ap = Ys + (wm * 32 + mt * 16 + lg) * SY + (kt * 2 + ks) * 8 + lr;
                    a[mt][0] = ap[0];
                    a[mt][1] = ap[8 * SY];
                    a[mt][2] = ap[4];
                    a[mt][3] = ap[8 * SY + 4];
                }
                #pragma unroll
                for (int nt = 0; nt < 8; nt++) {
                    const unsigned* bp = Bb + (ks * 8 + lr) * SB + wn * 64 + nt * 8 + lg;
                    unsigned b0 = bp[0];
                    unsigned b1v = bp[4 * SB];
                    MMA_F16(acc[0][nt], a[0], b0, b1v);
                    MMA_F16(acc[1][nt], a[1], b0, b1v);
                }
            }
            if (kt < 3) {
                unsigned* Bd = Bs + (cur ^ 1) * BBUF;
                #pragma unroll
                for (int j = 0; j < 2; j++) {
                    int f = tid + j * 256;
                    int ng = f & 31, k2 = f >> 5;
                    uint4 u;
                    u.x = fh2(rb0[j].x, rb1[j].x); u.y = fh2(rb0[j].y, rb1[j].y);
                    u.z = fh2(rb0[j].z, rb1[j].z); u.w = fh2(rb0[j].w, rb1[j].w);
                    *(uint4*)(Bd + k2 * SB + ng * 4) = u;
                }
            }
            __syncthreads();
        }

        // gelu + b1 -> Hs (fp16)
        #pragma unroll
        for (int mt = 0; mt < 2; mt++) {
            #pragma unroll
            for (int nt = 0; nt < 8; nt++) {
                int rloc = wm * 32 + mt * 16 + lg;
                int cu = wn * 32 + nt * 4 + lr;   // u32 column index
                float bb0 = b1[cch * 128 + cu * 2];
                float bb1 = b1[cch * 128 + cu * 2 + 1];
                Hs[rloc * SY + cu] =
                    fh2(gelu_f(acc[mt][nt][0] + bb0), gelu_f(acc[mt][nt][1] + bb1));
                Hs[(rloc + 8) * SY + cu] =
                    fh2(gelu_f(acc[mt][nt][2] + bb0), gelu_f(acc[mt][nt][3] + bb1));
            }
        }
        __syncthreads();

        // ---- phase 2: acc2 += H @ W2[cch*128 .. +128, :] ----
        #pragma unroll
        for (int j = 0; j < 2; j++) {
            int f = tid + j * 256;
            int ng = f & 31, k2 = f >> 5;
            float4 w0 = *(const float4*)(W2 + (size_t)(cch * 128 + k2 * 2) * DDIM + ng * 4);
            float4 w1 = *(const float4*)(W2 + (size_t)(cch * 128 + k2 * 2 + 1) * DDIM + ng * 4);
            uint4 u;
            u.x = fh2(w0.x, w1.x); u.y = fh2(w0.y, w1.y);
            u.z = fh2(w0.z, w1.z); u.w = fh2(w0.w, w1.w);
            *(uint4*)(Bs + k2 * SB + ng * 4) = u;
        }
        __syncthreads();

        #pragma unroll
        for (int kt = 0; kt < 4; kt++) {
            const int cur = kt & 1;
            if (kt < 3) {
                #pragma unroll
                for (int j = 0; j < 2; j++) {
                    int f = tid + j * 256;
                    int ng = f & 31, k2 = f >> 5;
                    int kr = cch * 128 + (kt + 1) * 32 + k2 * 2;
                    rb0[j] = *(const float4*)(W2 + (size_t)kr * DDIM + ng * 4);
                    rb1[j] = *(const float4*)(W2 + (size_t)(kr + 1) * DDIM + ng * 4);
                }
            }
            const unsigned* Bb = Bs + cur * BBUF;
            #pragma unroll
            for (int ks = 0; ks < 2; ks++) {
                unsigned a[2][4];
                #pragma unroll
                for (int mt = 0; mt < 2; mt++) {
                    const unsigned* ap = Hs + (wm * 32 + mt * 16 + lg) * SY + (kt * 2 + ks) * 8 + lr;
                    a[mt][0] = ap[0];
                    a[mt][1] = ap[8 * SY];
                    a[mt][2] = ap[4];
                    a[mt][3] = ap[8 * SY + 4];
                }
                #pragma unroll
                for (int nt = 0; nt < 8; nt++) {
                    const unsigned* bp = Bb + (ks * 8 + lr) * SB + wn * 64 + nt * 8 + lg;
                    unsigned b0 = bp[0];
                    unsigned b1v = bp[4 * SB];
                    MMA_F16(acc2[0][nt], a[0], b0, b1v);
                    MMA_F16(acc2[1][nt], a[1], b0, b1v);
                }
            }
            if (kt < 3) {
                unsigned* Bd = Bs + (cur ^ 1) * BBUF;
                #pragma unroll
                for (int j = 0; j < 2; j++) {
                    int f = tid + j * 256;
                    int ng = f & 31, k2 = f >> 5;
                    uint4 u;
                    u.x = fh2(rb0[j].x, rb1[j].x); u.y = fh2(rb0[j].y, rb1[j].y);
                    u.z = fh2(rb0[j].z, rb1[j].z); u.w = fh2(rb0[j].w, rb1[j].w);
                    *(uint4*)(Bd + k2 * SB + ng * 4) = u;
                }
            }
            __syncthreads();
        }
    }

    // epilogue: + b2 + res
    #pragma unroll
    for (int mt = 0; mt < 2; mt++) {
        #pragma unroll
        for (int nt = 0; nt < 8; nt++) {
            int r = row0 + wm * 32 + mt * 16 + lg;
            int c = wn * 64 + nt * 8 + lr * 2;
            float bb0 = b2[c], bb1 = b2[c + 1];
            if (r < n) {
                float2 rr = *(const float2*)(res + (size_t)r * DDIM + c);
                *(float2*)(C + (size_t)r * DDIM + c) =
                    make_float2(acc2[mt][nt][0] + bb0 + rr.x,
                                acc2[mt][nt][1] + bb1 + rr.y);
            }
            if (r + 8 < n) {
                float2 rr = *(const float2*)(res + (size_t)(r + 8) * DDIM + c);
                *(float2*)(C + (size_t)(r + 8) * DDIM + c) =
                    make_float2(acc2[mt][nt][2] + bb0 + rr.x,
                                acc2[mt][nt][3] + bb1 + rr.y);
            }
        }
    }
}

// ---------------- launch ----------------
extern "C" void kernel_launch(void* const* d_in, const int* in_sizes, int n_in,
                              void* d_out, int out_size) {
    const float* node_feature = (const float*)d_in[0];
    const float* dist_attn    = (const float*)d_in[1];
    const float* path_attn    = (const float*)d_in[2];
    const int*   src          = (const int*)d_in[3];
    const int*   dst          = (const int*)d_in[4];
    const float* ln1_g        = (const float*)d_in[5];
    const float* ln1_b        = (const float*)d_in[6];
    const float* qkv_w        = (const float*)d_in[7];
    const float* qkv_b        = (const float*)d_in[8];
    const float* in_proj_w    = (const float*)d_in[9];
    const float* in_proj_b    = (const float*)d_in[10];
    const float* res_ln_g     = (const float*)d_in[11];
    const float* res_ln_b     = (const float*)d_in[12];
    const float* mlp_w1       = (const float*)d_in[13];
    const float* mlp_b1       = (const float*)d_in[14];
    const float* mlp_w2       = (const float*)d_in[15];
    const float* mlp_b2       = (const float*)d_in[16];
    float* out = (float*)d_out;

    cudaFuncSetAttribute(gemm_tc<0>, cudaFuncAttributeMaxDynamicSharedMemorySize, GM_SMEM0);
    cudaFuncSetAttribute(gemm_tc<1>, cudaFuncAttributeMaxDynamicSharedMemorySize, GM_SMEM1);
    cudaFuncSetAttribute(fmlp_kernel, cudaFuncAttributeMaxDynamicSharedMemorySize, FM_SMEM);

    void* p;
    cudaGetSymbolAddress(&p, g_h);    float*  ph   = (float*)p;
    cudaGetSymbolAddress(&p, g_hh);   __half* phh  = (__half*)p;
    cudaGetSymbolAddress(&p, g_qkv);  __half* pqkv = (__half*)p;
    cudaGetSymbolAddress(&p, g_agg);  __half* pagg = (__half*)p;
    cudaGetSymbolAddress(&p, g_x);    float*  px   = (float*)p;
    cudaGetSymbolAddress(&p, g_yh);   __half* pyh  = (__half*)p;

    const int RB = (NN + 127) / 128;           // 391 row blocks
    const int LN_BLOCKS = (NN + 7) / 8;
    const int E_BLOCKS  = (EE + 255) / 256;
    const int ATTN_BLOCKS = (NN * 32 + 255) / 256;

    // CSR build (+ precompute of src & dist+path in CSR order)
    zero_ln_kernel<<<NBLK + LN_BLOCKS, 256>>>(node_feature, ln1_g, ln1_b, ph, phh);
    hist_kernel<<<E_BLOCKS, 256>>>(dst);
    scanA_kernel<<<NB, 256>>>();
    scanBC_kernel<<<NB, 256>>>();
    scatter_kernel<<<E_BLOCKS, 256>>>(src, dst, dist_attn, path_attn);

    // main pipeline
    gemm_tc<0><<<dim3(3, RB), 256, GM_SMEM0>>>(phh, qkv_w, qkv_b, nullptr, pqkv,
                                               nullptr, nullptr, nullptr, NN, 384, 128);
    attn_kernel<<<ATTN_BLOCKS, 256>>>();
    gemm_tc<1><<<dim3(1, RB), 256, GM_SMEM1>>>(pagg, in_proj_w, in_proj_b, ph, px,
                                               res_ln_g, res_ln_b, pyh, NN, 128, 128);
    fmlp_kernel<<<RB, 256, FM_SMEM>>>(pyh, mlp_w1, mlp_b1, mlp_w2, mlp_b2, px, out, NN);
}